// round 4
// baseline (speedup 1.0000x reference)
#include <cuda_runtime.h>
#include <math.h>

#define BS 8
#define F 16
#define NI 24
#define L 16384            // H*W
#define BPB 32             // blocks per batch
#define NBLK (BS * BPB)    // 256 total blocks -- MUST be <= 2 * numSMs (152*2=304)
#define THREADS 256

// ---------------- scratch (no allocations; zero-initialized at load) ----------------
__device__ float    g_sums[BS][NI][F];
__device__ float    g_counts[BS][NI];
__device__ float    g_varnum[BS];
__device__ unsigned g_cnt1;
__device__ unsigned g_cnt2;

__global__ void __launch_bounds__(THREADS, 2)
k_fused(const float* __restrict__ inp, const int* __restrict__ tgt,
        const int* __restrict__ nobj, float* __restrict__ out)
{
    const int b    = blockIdx.x >> 5;        // batch
    const int blkb = blockIdx.x & 31;        // block within batch
    const int tid  = threadIdx.x;
    const int warp = tid >> 5;
    const int lane = tid & 31;
    const int f    = lane & 15;
    const int half = lane >> 4;
    const int nb   = __ldg(nobj + b);

    __shared__ float      sh_w[8][NI][32];   // 24KB: per-warp partials; later aliased to means
    __shared__ unsigned   smask[8][2][NI];   // 1.5KB: this block's pixel masks
    __shared__ ulonglong2 msh2[NI * 4];      // negated means of batch b, packed f32x2
    __shared__ float      red[8];
    __shared__ float      sv[BS], sr[BS], shg[BS];
    __shared__ bool       sflag;

    // ================= Phase A: sums / counts / masks =================
    float acc[NI];
#pragma unroll
    for (int i = 0; i < NI; i++) acc[i] = 0.f;

#pragma unroll
    for (int q = 0; q < 2; q++) {
        const int g  = (blkb * 8 + warp) * 2 + q;      // pixel-group 0..511
        const int l0 = g * 32;

        // 16 contiguous pixels of this lane's feature row (4x LDG.128)
        const float* ip = inp + ((size_t)b * F + f) * L + l0 + half * 16;
        float4 v0 = *(const float4*)(ip + 0);
        float4 v1 = *(const float4*)(ip + 4);
        float4 v2 = *(const float4*)(ip + 8);
        float4 v3 = *(const float4*)(ip + 12);
        float preg[16] = {v0.x, v0.y, v0.z, v0.w, v1.x, v1.y, v1.z, v1.w,
                          v2.x, v2.y, v2.z, v2.w, v3.x, v3.y, v3.z, v3.w};

        // batched target loads (lane = pixel), valid instances only
        const int* tb = tgt + ((size_t)b * NI) * L + l0 + lane;
        int tval[NI];
#pragma unroll
        for (int i = 0; i < NI; i++)
            tval[i] = (i < nb) ? tb[(size_t)i * L] : 0;

#pragma unroll
        for (int i = 0; i < NI; i++) {
            if (i >= nb) break;                          // nb warp-uniform
            unsigned mi = __ballot_sync(0xffffffffu, tval[i] != 0);
            if (lane == 0) smask[warp][q][i] = mi;
            unsigned sub = (mi >> (half * 16)) & 0xffffu;
            float a0 = 0.f, a1 = 0.f;                    // dual chains for ILP
#pragma unroll
            for (int k = 0; k < 16; k += 2) {
                if ((sub >> k) & 1u)       a0 += preg[k];
                if ((sub >> (k + 1)) & 1u) a1 += preg[k + 1];
            }
            acc[i] += a0 + a1;
        }
    }
#pragma unroll
    for (int i = 0; i < NI; i++)
        sh_w[warp][i][lane] = (i < nb) ? acc[i] : 0.f;
    __syncthreads();

    // block reduce -> one global atomic per (i,f); counts from mask popc
    for (int idx = tid; idx < NI * F; idx += THREADS) {
        int i = idx >> 4, ff = idx & 15;
        if (i < nb) {
            float s = 0.f;
#pragma unroll
            for (int w = 0; w < 8; w++)
                s += sh_w[w][i][ff] + sh_w[w][i][ff + 16];
            atomicAdd(&g_sums[b][i][ff], s);
        }
    }
    if (tid < NI && tid < nb) {
        float c = 0.f;
#pragma unroll
        for (int w = 0; w < 8; w++)
            c += (float)(__popc(smask[w][0][tid]) + __popc(smask[w][1][tid]));
        atomicAdd(&g_counts[b][tid], c);
    }

    // ================= grid sync (all 256 blocks co-resident) =================
    __threadfence();
    __syncthreads();
    if (tid == 0) {
        atomicAdd(&g_cnt1, 1u);
        while (*(volatile unsigned*)&g_cnt1 < (unsigned)NBLK) __nanosleep(64);
    }
    __syncthreads();

    // ================= Phase B: negated means of batch b (per block, local) =====
    for (int idx = tid; idx < NI * F; idx += THREADS) {
        int i = idx >> 4;
        float mval = 0.f;
        if (i < nb) {
            float c = __ldcg(&g_counts[b][i]);
            mval = __ldcg(&g_sums[b][i][idx & 15]) / (c > 0.f ? c : 1.f);
        }
        ((float*)msh2)[idx] = -mval;
    }
    __syncthreads();

    // ================= Phase C: var_num (2 pixels / thread, f32x2) =============
    float local = 0.f;
#pragma unroll
    for (int q = 0; q < 2; q++) {
        const int l = ((blkb * 8 + warp) * 2 + q) * 32 + lane;
        const float* ib = inp + (size_t)b * F * L + l;   // L2-resident after A
        unsigned long long p2[8];
#pragma unroll
        for (int j = 0; j < 8; j++) {
            float lo = ib[(size_t)(2 * j) * L];
            float hi = ib[(size_t)(2 * j + 1) * L];
            asm("mov.b64 %0,{%1,%2};" : "=l"(p2[j]) : "f"(lo), "f"(hi));
        }
#pragma unroll
        for (int i = 0; i < NI; i++) {
            if (i >= nb) break;
            unsigned mi = smask[warp][q][i];             // broadcast LDS
            if ((mi >> lane) & 1u) {
                unsigned long long ssa = 0ull, ssb = 0ull;
#pragma unroll
                for (int qq = 0; qq < 4; qq++) {
                    ulonglong2 mv = msh2[i * 4 + qq];    // broadcast LDS.128
                    unsigned long long d0, d1;
                    asm("add.rn.f32x2 %0,%1,%2;" : "=l"(d0) : "l"(p2[2 * qq]),     "l"(mv.x));
                    asm("add.rn.f32x2 %0,%1,%2;" : "=l"(d1) : "l"(p2[2 * qq + 1]), "l"(mv.y));
                    asm("fma.rn.f32x2 %0,%1,%2,%3;" : "=l"(ssa) : "l"(d0), "l"(d0), "l"(ssa));
                    asm("fma.rn.f32x2 %0,%1,%2,%3;" : "=l"(ssb) : "l"(d1), "l"(d1), "l"(ssb));
                }
                float alo, ahi, blo, bhi;
                asm("mov.b64 {%0,%1},%2;" : "=f"(alo), "=f"(ahi) : "l"(ssa));
                asm("mov.b64 {%0,%1},%2;" : "=f"(blo), "=f"(bhi) : "l"(ssb));
                float ss = (alo + ahi) + (blo + bhi);
                if (ss > 0.25f) {                        // delta_v^2
                    float h = sqrtf(ss) - 0.5f;
                    local += h * h;
                }
            }
        }
    }

    // block reduce -> per-batch atomic
#pragma unroll
    for (int o = 16; o > 0; o >>= 1)
        local += __shfl_down_sync(0xffffffffu, local, o);
    if (lane == 0) red[warp] = local;
    __syncthreads();
    if (tid < 8) {
        float v = red[tid];
#pragma unroll
        for (int o = 4; o > 0; o >>= 1)
            v += __shfl_down_sync(0xffu, v, o);
        if (tid == 0) atomicAdd(&g_varnum[b], v);
    }

    // ================= last block: stats + final + re-zero =================
    __threadfence();
    __syncthreads();
    if (tid == 0)
        sflag = (atomicAdd(&g_cnt2, 1u) == (unsigned)NBLK - 1u);
    __syncthreads();
    if (!sflag) return;

    // means for ALL batches into shared (alias sh_w: 3072 floats <= 6144)
    float* fme = &sh_w[0][0][0];
    for (int idx = tid; idx < BS * NI * F; idx += THREADS) {
        int bb = idx / (NI * F);
        int i  = (idx % (NI * F)) >> 4;
        float mval = 0.f;
        if (i < __ldg(nobj + bb)) {
            float c = __ldcg(&g_counts[bb][i]);
            mval = __ldcg(&((float*)g_sums)[idx]) / (c > 0.f ? c : 1.f);
        }
        fme[idx] = mval;
    }
    if (tid < BS) { sv[tid] = 0.f; sr[tid] = 0.f; shg[tid] = 0.f; }
    __syncthreads();

    // varden + reg
    for (int idx = tid; idx < BS * NI; idx += THREADS) {
        int bb = idx / NI, i = idx % NI;
        if (i < __ldg(nobj + bb)) {
            atomicAdd(&sv[bb], __ldcg(&g_counts[bb][i]));
            float ss = 0.f;
#pragma unroll
            for (int ff = 0; ff < F; ff++) {
                float m = fme[(bb * NI + i) * F + ff];
                ss += m * m;
            }
            atomicAdd(&sr[bb], ss > 0.f ? sqrtf(ss) : 0.f);
        }
    }
    // pairwise hinge
    for (int idx = tid; idx < BS * NI * NI; idx += THREADS) {
        int bb = idx / (NI * NI);
        int r  = idx % (NI * NI);
        int i = r / NI, j = r % NI;
        int nbb = __ldg(nobj + bb);
        if (i < nbb && j < nbb && i != j) {
            float ss = 0.f;
#pragma unroll
            for (int ff = 0; ff < F; ff++) {
                float d = fme[(bb * NI + i) * F + ff] - fme[(bb * NI + j) * F + ff];
                ss += d * d;
            }
            float dn = ss > 0.f ? sqrtf(ss) : 0.f;
            float h = fmaxf(3.0f - dn, 0.f);             // margin = 2*delta_d
            atomicAdd(&shg[bb], h * h);
        }
    }
    __syncthreads();

    if (tid == 0) {
        float var_t = 0.f, dist_t = 0.f, reg_t = 0.f;
        for (int bb = 0; bb < BS; bb++) {
            var_t += __ldcg(&g_varnum[bb]) / sv[bb];
            float nf = (float)__ldg(nobj + bb);
            float denom = nf > 1.f ? nf * (nf - 1.f) : 1.f;
            dist_t += (nf > 1.f) ? shg[bb] / denom : 0.f;
            reg_t += sr[bb] / nf;
        }
        out[0] = var_t / BS + dist_t / BS + 0.001f * (reg_t / BS);
    }

    // re-zero scratch so every graph replay starts from the load-time state
    for (int idx = tid; idx < BS * NI * F; idx += THREADS)
        ((float*)g_sums)[idx] = 0.f;
    for (int idx = tid; idx < BS * NI; idx += THREADS)
        ((float*)g_counts)[idx] = 0.f;
    if (tid < BS) g_varnum[tid] = 0.f;
    __threadfence();
    __syncthreads();
    if (tid == 0) { g_cnt1 = 0u; g_cnt2 = 0u; }
}

// ---------------- launch ----------------
extern "C" void kernel_launch(void* const* d_in, const int* in_sizes, int n_in,
                              void* d_out, int out_size) {
    const float* inp  = (const float*)d_in[0];   // (8,16,128,128) f32
    const int*   tgt  = (const int*)d_in[1];     // (8,24,128,128) i32
    const int*   nobj = (const int*)d_in[2];     // (8,1) i32
    (void)in_sizes; (void)n_in; (void)out_size;

    k_fused<<<NBLK, THREADS>>>(inp, tgt, nobj, (float*)d_out);
}